// round 1
// baseline (speedup 1.0000x reference)
#include <cuda_runtime.h>
#include <cuda_bf16.h>
#include <math.h>

// Problem constants
#define SLEN 1024
#define BSZ  8
#define IDIM 256
#define HDIM 512
#define NHEAD 8
#define HD 64
#define FFDIM 1024
#define NLAYER 4
#define NTOK (SLEN*BSZ)   // 8192

// ---------------- scratch (device globals; no allocation allowed) -----------
__device__ float g_xin [NTOK * IDIM];    //  8 MB
__device__ float g_x   [NTOK * HDIM];    // 16 MB
__device__ float g_tmp [NTOK * HDIM];    // 16 MB
__device__ float g_qkv [NTOK * 3*HDIM];  // 48 MB
__device__ float g_attn[NTOK * HDIM];    // 16 MB
__device__ float g_ff  [NTOK * FFDIM];   // 32 MB

// ---------------- transpose nodes (S,B,I) -> x_in (B*S, I) ------------------
__global__ void transpose_kernel(const float* __restrict__ nodes, float* __restrict__ xin)
{
    int token = blockIdx.x;          // token = b*S + s
    int b = token >> 10;
    int s = token & 1023;
    xin[(size_t)token * IDIM + threadIdx.x] =
        nodes[((size_t)s * BSZ + b) * IDIM + threadIdx.x];
}

// ---------------- generic tiled SGEMM: C[M,N] = A[M,K] @ W[N,K]^T + bias ----
#define BM 64
#define BN 64
#define BK 32
__global__ __launch_bounds__(256) void gemm_bias_kernel(
    const float* __restrict__ A, const float* __restrict__ W,
    const float* __restrict__ bias, float* __restrict__ C,
    int M, int N, int K, int relu)
{
    __shared__ __align__(16) float As[BK][BM + 4];
    __shared__ __align__(16) float Ws[BK][BN + 4];
    int tid = threadIdx.x;
    int tx = tid & 15;       // 0..15 -> col group
    int ty = tid >> 4;       // 0..15 -> row group
    int row0 = blockIdx.y * BM;
    int col0 = blockIdx.x * BN;

    float acc[4][4];
#pragma unroll
    for (int i = 0; i < 4; i++)
#pragma unroll
        for (int j = 0; j < 4; j++) acc[i][j] = 0.f;

    for (int k0 = 0; k0 < K; k0 += BK) {
#pragma unroll
        for (int i = tid; i < BM * BK; i += 256) {
            int r = i >> 5, c = i & 31;
            As[c][r] = A[(size_t)(row0 + r) * K + k0 + c];
        }
#pragma unroll
        for (int i = tid; i < BN * BK; i += 256) {
            int r = i >> 5, c = i & 31;
            Ws[c][r] = W[(size_t)(col0 + r) * K + k0 + c];
        }
        __syncthreads();
#pragma unroll
        for (int kk = 0; kk < BK; kk++) {
            float4 a4 = *reinterpret_cast<const float4*>(&As[kk][ty * 4]);
            float4 w4 = *reinterpret_cast<const float4*>(&Ws[kk][tx * 4]);
            float a[4] = {a4.x, a4.y, a4.z, a4.w};
            float w[4] = {w4.x, w4.y, w4.z, w4.w};
#pragma unroll
            for (int i = 0; i < 4; i++)
#pragma unroll
                for (int j = 0; j < 4; j++) acc[i][j] += a[i] * w[j];
        }
        __syncthreads();
    }
#pragma unroll
    for (int i = 0; i < 4; i++) {
        int r = row0 + ty * 4 + i;
#pragma unroll
        for (int j = 0; j < 4; j++) {
            int c = col0 + tx * 4 + j;
            float v = acc[i][j] + bias[c];
            if (relu) v = fmaxf(v, 0.f);
            C[(size_t)r * N + c] = v;
        }
    }
}

// ---------------- LayerNorm row kernel (H=512), optional residual -----------
__global__ __launch_bounds__(256) void ln_kernel(
    const float* __restrict__ y, const float* __restrict__ res,
    const float* __restrict__ g, const float* __restrict__ bta,
    float* __restrict__ out)
{
    __shared__ float rs[8], rq[8], stats[2];
    int tid = threadIdx.x;
    int lane = tid & 31, wid = tid >> 5;
    size_t base = (size_t)blockIdx.x * HDIM;

    float v0 = y[base + tid];
    float v1 = y[base + tid + 256];
    if (res) { v0 += res[base + tid]; v1 += res[base + tid + 256]; }

    float sum = v0 + v1;
    float sq  = v0 * v0 + v1 * v1;
#pragma unroll
    for (int off = 16; off > 0; off >>= 1) {
        sum += __shfl_xor_sync(0xffffffffu, sum, off);
        sq  += __shfl_xor_sync(0xffffffffu, sq,  off);
    }
    if (lane == 0) { rs[wid] = sum; rq[wid] = sq; }
    __syncthreads();
    if (tid == 0) {
        float S = 0.f, Q = 0.f;
#pragma unroll
        for (int i = 0; i < 8; i++) { S += rs[i]; Q += rq[i]; }
        float mean = S * (1.0f / HDIM);
        float var  = Q * (1.0f / HDIM) - mean * mean;
        stats[0] = mean;
        stats[1] = rsqrtf(var + 1e-5f);
    }
    __syncthreads();
    float mean = stats[0], inv = stats[1];
    out[base + tid]       = (v0 - mean) * inv * g[tid]       + bta[tid];
    out[base + tid + 256] = (v1 - mean) * inv * g[tid + 256] + bta[tid + 256];
}

// ---------------- flash attention: 16 q-rows per CTA, 128-key tiles ---------
#define QT 16
#define KT 128
__global__ __launch_bounds__(512) void attn_kernel(
    const float* __restrict__ qkv, const int* __restrict__ dist,
    float* __restrict__ out)
{
    __shared__ float Kt[KT][HD + 1];   // shared between K and V phases
    __shared__ float P [QT][KT];
    __shared__ float Qs[QT][HD];

    int tid  = threadIdx.x;
    int lane = tid & 31;
    int w    = tid >> 5;               // warp = q-row within tile
    int q0 = blockIdx.x * QT;
    int h  = blockIdx.y;
    int b  = blockIdx.z;
    size_t tokbase = (size_t)b * SLEN;

    for (int i = tid; i < QT * HD; i += 512) {
        int qi = i >> 6, d = i & 63;
        Qs[qi][d] = qkv[(tokbase + q0 + qi) * (3 * HDIM) + h * HD + d];
    }

    int myq = q0 + w;
    const int* drow = (h < 6)
        ? dist + ((size_t)b * SLEN + myq) * SLEN    // short/long: dist[b, q, :]
        : dist + (size_t)b * SLEN * SLEN;           // global:     dist[b, 0, :]

    float m = -1e30f, l = 0.f;
    float o0 = 0.f, o1 = 0.f;

    for (int t = 0; t < SLEN / KT; t++) {
        int k0 = t * KT;
        __syncthreads();                 // prev accumulate done / Qs visible
        for (int i = tid; i < KT * HD; i += 512) {
            int j = i >> 6, d = i & 63;
            Kt[j][d] = qkv[(tokbase + k0 + j) * (3 * HDIM) + HDIM + h * HD + d];
        }
        __syncthreads();

        float s[4];
#pragma unroll
        for (int i = 0; i < 4; i++) {
            int j = lane + i * 32;
            float acc = 0.f;
#pragma unroll
            for (int d = 0; d < HD; d++) acc += Qs[w][d] * Kt[j][d];
            s[i] = acc * 0.125f;         // 1/sqrt(64)
            int k = k0 + j;
            int dv = drow[k];
            bool allowed = (h < 4) ? (dv == 1) : (dv >= 1);
            if (k == myq) allowed = true;
            if (!allowed) s[i] += -1e9f;
        }
        float tmax = fmaxf(fmaxf(s[0], s[1]), fmaxf(s[2], s[3]));
#pragma unroll
        for (int off = 16; off > 0; off >>= 1)
            tmax = fmaxf(tmax, __shfl_xor_sync(0xffffffffu, tmax, off));
        float newm = fmaxf(m, tmax);
        float c = __expf(m - newm);
        float psum = 0.f;
#pragma unroll
        for (int i = 0; i < 4; i++) {
            float p = __expf(s[i] - newm);
            P[w][lane + i * 32] = p;
            psum += p;
        }
#pragma unroll
        for (int off = 16; off > 0; off >>= 1)
            psum += __shfl_xor_sync(0xffffffffu, psum, off);
        l = l * c + psum;
        m = newm;
        __syncthreads();                 // K reads done; P visible

        for (int i = tid; i < KT * HD; i += 512) {
            int j = i >> 6, d = i & 63;
            Kt[j][d] = qkv[(tokbase + k0 + j) * (3 * HDIM) + 2 * HDIM + h * HD + d];
        }
        __syncthreads();

        float a0 = 0.f, a1 = 0.f;
#pragma unroll 8
        for (int j = 0; j < KT; j++) {
            float p = P[w][j];
            a0 += p * Kt[j][lane];
            a1 += p * Kt[j][lane + 32];
        }
        o0 = o0 * c + a0;
        o1 = o1 * c + a1;
    }
    float inv = 1.f / l;
    size_t obase = (tokbase + myq) * HDIM + h * HD;
    out[obase + lane]      = o0 * inv;
    out[obase + lane + 32] = o1 * inv;
}

// ---------------- final batchnorm over batch of 8 at s=0 --------------------
__global__ void bn_kernel(const float* __restrict__ x, const float* __restrict__ g,
                          const float* __restrict__ bta, float* __restrict__ out)
{
    int c = threadIdx.x;      // 512 threads
    float v[BSZ];
    float s = 0.f;
#pragma unroll
    for (int b = 0; b < BSZ; b++) {
        v[b] = x[((size_t)b * SLEN) * HDIM + c];
        s += v[b];
    }
    float mean = s * (1.0f / BSZ);
    float q = 0.f;
#pragma unroll
    for (int b = 0; b < BSZ; b++) { float d = v[b] - mean; q += d * d; }
    float inv = rsqrtf(q * (1.0f / BSZ) + 1e-5f);
#pragma unroll
    for (int b = 0; b < BSZ; b++)
        out[b * HDIM + c] = (v[b] - mean) * inv * g[c] + bta[c];
}

// ---------------- launcher --------------------------------------------------
extern "C" void kernel_launch(void* const* d_in, const int* in_sizes, int n_in,
                              void* d_out, int out_size)
{
    const float* nodes   = (const float*)d_in[0];
    const int*   dist    = (const int*)  d_in[1];
    const float* dense_w = (const float*)d_in[2];
    const float* dense_b = (const float*)d_in[3];
    const float* dln_g   = (const float*)d_in[4];
    const float* dln_b   = (const float*)d_in[5];
    const float* qkv_w   = (const float*)d_in[6];
    const float* qkv_b   = (const float*)d_in[7];
    const float* out_w   = (const float*)d_in[8];
    const float* out_b   = (const float*)d_in[9];
    const float* ln1_g   = (const float*)d_in[10];
    const float* ln1_b   = (const float*)d_in[11];
    const float* w1      = (const float*)d_in[12];
    const float* b1      = (const float*)d_in[13];
    const float* w2      = (const float*)d_in[14];
    const float* b2      = (const float*)d_in[15];
    const float* ln2_g   = (const float*)d_in[16];
    const float* ln2_b   = (const float*)d_in[17];
    const float* bn_g    = (const float*)d_in[18];
    const float* bn_b    = (const float*)d_in[19];
    float* out = (float*)d_out;

    float *xin, *x, *tmp, *qkv, *attn, *ff;
    cudaGetSymbolAddress((void**)&xin,  g_xin);
    cudaGetSymbolAddress((void**)&x,    g_x);
    cudaGetSymbolAddress((void**)&tmp,  g_tmp);
    cudaGetSymbolAddress((void**)&qkv,  g_qkv);
    cudaGetSymbolAddress((void**)&attn, g_attn);
    cudaGetSymbolAddress((void**)&ff,   g_ff);

    // dense + LN
    transpose_kernel<<<NTOK, IDIM>>>(nodes, xin);
    gemm_bias_kernel<<<dim3(HDIM / BN, NTOK / BM), 256>>>(
        xin, dense_w, dense_b, tmp, NTOK, HDIM, IDIM, 0);
    ln_kernel<<<NTOK, 256>>>(tmp, nullptr, dln_g, dln_b, x);

    for (int l = 0; l < NLAYER; l++) {
        // QKV projection
        gemm_bias_kernel<<<dim3(3 * HDIM / BN, NTOK / BM), 256>>>(
            x, qkv_w + (size_t)l * 3 * HDIM * HDIM, qkv_b + (size_t)l * 3 * HDIM,
            qkv, NTOK, 3 * HDIM, HDIM, 0);
        // attention
        attn_kernel<<<dim3(SLEN / QT, NHEAD, BSZ), 512>>>(qkv, dist, attn);
        // output projection + residual LN
        gemm_bias_kernel<<<dim3(HDIM / BN, NTOK / BM), 256>>>(
            attn, out_w + (size_t)l * HDIM * HDIM, out_b + (size_t)l * HDIM,
            tmp, NTOK, HDIM, HDIM, 0);
        ln_kernel<<<NTOK, 256>>>(tmp, x, ln1_g + (size_t)l * HDIM,
                                 ln1_b + (size_t)l * HDIM, x);
        // FFN
        gemm_bias_kernel<<<dim3(FFDIM / BN, NTOK / BM), 256>>>(
            x, w1 + (size_t)l * FFDIM * HDIM, b1 + (size_t)l * FFDIM,
            ff, NTOK, FFDIM, HDIM, 1);
        gemm_bias_kernel<<<dim3(HDIM / BN, NTOK / BM), 256>>>(
            ff, w2 + (size_t)l * HDIM * FFDIM, b2 + (size_t)l * HDIM,
            tmp, NTOK, HDIM, FFDIM, 0);
        ln_kernel<<<NTOK, 256>>>(tmp, x, ln2_g + (size_t)l * HDIM,
                                 ln2_b + (size_t)l * HDIM, x);
    }

    bn_kernel<<<1, HDIM>>>(x, bn_g, bn_b, out);
}

// round 2
// speedup vs baseline: 5.1029x; 5.1029x over previous
#include <cuda_runtime.h>
#include <math.h>
#include <stdint.h>

// Problem constants
#define SLEN 1024
#define BSZ  8
#define IDIM 256
#define HDIM 512
#define NHEAD 8
#define HD 64
#define FFDIM 1024
#define NLAYER 4
#define NTOK (SLEN*BSZ)   // 8192

// ---------------- scratch (device globals; no allocation allowed) -----------
__device__ float g_xin [NTOK * IDIM];
__device__ float g_x   [NTOK * HDIM];
__device__ float g_tmp [NTOK * HDIM];
__device__ float g_qkv [NTOK * 3*HDIM];
__device__ float g_attn[NTOK * HDIM];
__device__ float g_ff  [NTOK * FFDIM];

// ---------------- helpers ---------------------------------------------------
__device__ __forceinline__ uint32_t f2tf(float x){
    uint32_t r; asm("cvt.rna.tf32.f32 %0, %1;" : "=r"(r) : "f"(x)); return r;
}
__device__ __forceinline__ void mma8(float* c, const uint32_t* a, uint32_t b0, uint32_t b1){
    asm volatile(
        "mma.sync.aligned.m16n8k8.row.col.f32.tf32.tf32.f32 "
        "{%0,%1,%2,%3},{%4,%5,%6,%7},{%8,%9},{%0,%1,%2,%3};"
        : "+f"(c[0]),"+f"(c[1]),"+f"(c[2]),"+f"(c[3])
        : "r"(a[0]),"r"(a[1]),"r"(a[2]),"r"(a[3]),"r"(b0),"r"(b1));
}
__device__ __forceinline__ void cpa16(uint32_t s, const void* g){
    asm volatile("cp.async.cg.shared.global [%0], [%1], 16;" :: "r"(s),"l"(g));
}
__device__ __forceinline__ void cpacommit(){ asm volatile("cp.async.commit_group;"); }
__device__ __forceinline__ void cpawait1(){ asm volatile("cp.async.wait_group 1;"); }
__device__ __forceinline__ void cpawait0(){ asm volatile("cp.async.wait_group 0;"); }

// ---------------- transpose nodes (S,B,I) -> x_in (B*S, I) ------------------
__global__ void transpose_kernel(const float* __restrict__ nodes, float* __restrict__ xin)
{
    int token = blockIdx.x;
    int b = token >> 10;
    int s = token & 1023;
    xin[(size_t)token * IDIM + threadIdx.x] =
        nodes[((size_t)s * BSZ + b) * IDIM + threadIdx.x];
}

// ---------------- tf32 tensor-core GEMM: C[M,N] = A[M,K] @ W[N,K]^T + bias --
// CTA tile 128x64, BK=32, 256 threads = 8 warps (4m x 2n), warp tile 32x32.
// smem (dynamic): A[2][128][36], W[2][64][36] floats  (stride 36 => bank 4g+r)
__global__ __launch_bounds__(256) void gemm_tf32(
    const float* __restrict__ A, const float* __restrict__ W,
    const float* __restrict__ bias, float* __restrict__ C,
    int M, int N, int K, int relu)
{
    extern __shared__ float sm[];
    float* sA = sm;                 // 2 * 4608
    float* sW = sm + 2*4608;        // 2 * 2304

    const int tid  = threadIdx.x;
    const int lane = tid & 31, wid = tid >> 5;
    const int g = lane >> 2, r = lane & 3;
    const int wm = wid & 3, wn = wid >> 2;
    const int row0 = blockIdx.y * 128, col0 = blockIdx.x * 64;

    const uint32_t sAb = (uint32_t)__cvta_generic_to_shared(sA);
    const uint32_t sWb = (uint32_t)__cvta_generic_to_shared(sW);

    float c[2][4][4];
#pragma unroll
    for (int i=0;i<2;i++)
#pragma unroll
        for (int j=0;j<4;j++)
#pragma unroll
            for (int k=0;k<4;k++) c[i][j][k] = 0.f;

    const int nbk = K >> 5;

    auto issue = [&](int bk, int st){
        const float* Ap = A + (size_t)row0 * K + bk*32;
#pragma unroll
        for (int p=0;p<4;p++){
            int idx = tid + p*256;
            int rowA = idx >> 3, c4 = (idx & 7) << 2;
            cpa16(sAb + (uint32_t)(st*4608 + rowA*36 + c4)*4, Ap + (size_t)rowA*K + c4);
        }
        const float* Wp = W + (size_t)col0 * K + bk*32;
#pragma unroll
        for (int p=0;p<2;p++){
            int idx = tid + p*256;
            int rowW = idx >> 3, c4 = (idx & 7) << 2;
            cpa16(sWb + (uint32_t)(st*2304 + rowW*36 + c4)*4, Wp + (size_t)rowW*K + c4);
        }
        cpacommit();
    };

    issue(0, 0);
    for (int bk = 0; bk < nbk; bk++){
        int st = bk & 1;
        if (bk+1 < nbk){ issue(bk+1, st^1); cpawait1(); }
        else           { cpawait0(); }
        __syncthreads();
        const float* a_s = sA + st*4608;
        const float* w_s = sW + st*2304;
#pragma unroll
        for (int kc=0; kc<4; kc++){
            uint32_t a[2][4];
#pragma unroll
            for (int mt=0; mt<2; mt++){
                int mb = wm*32 + mt*16;
                a[mt][0] = f2tf(a_s[(mb+g  )*36 + kc*8 + r  ]);
                a[mt][1] = f2tf(a_s[(mb+g+8)*36 + kc*8 + r  ]);
                a[mt][2] = f2tf(a_s[(mb+g  )*36 + kc*8 + r+4]);
                a[mt][3] = f2tf(a_s[(mb+g+8)*36 + kc*8 + r+4]);
            }
#pragma unroll
            for (int nt=0; nt<4; nt++){
                int nb = wn*32 + nt*8;
                uint32_t b0 = f2tf(w_s[(nb+g)*36 + kc*8 + r  ]);
                uint32_t b1 = f2tf(w_s[(nb+g)*36 + kc*8 + r+4]);
                mma8(c[0][nt], a[0], b0, b1);
                mma8(c[1][nt], a[1], b0, b1);
            }
        }
        __syncthreads();
    }

#pragma unroll
    for (int mt=0; mt<2; mt++){
#pragma unroll
        for (int nt=0; nt<4; nt++){
            int rr = row0 + wm*32 + mt*16 + g;
            int cc = col0 + wn*32 + nt*8 + 2*r;
            float b0 = bias[cc], b1 = bias[cc+1];
            float v0 = c[mt][nt][0] + b0, v1 = c[mt][nt][1] + b1;
            float v2 = c[mt][nt][2] + b0, v3 = c[mt][nt][3] + b1;
            if (relu){ v0=fmaxf(v0,0.f); v1=fmaxf(v1,0.f); v2=fmaxf(v2,0.f); v3=fmaxf(v3,0.f); }
            *(float2*)(C + (size_t)rr*N + cc)     = make_float2(v0, v1);
            *(float2*)(C + (size_t)(rr+8)*N + cc) = make_float2(v2, v3);
        }
    }
}

// ---------------- LayerNorm row kernel (H=512), optional residual -----------
__global__ __launch_bounds__(256) void ln_kernel(
    const float* __restrict__ y, const float* __restrict__ res,
    const float* __restrict__ g, const float* __restrict__ bta,
    float* __restrict__ out)
{
    __shared__ float rs[8], rq[8], stats[2];
    int tid = threadIdx.x;
    int lane = tid & 31, wid = tid >> 5;
    size_t base = (size_t)blockIdx.x * HDIM;

    float v0 = y[base + tid];
    float v1 = y[base + tid + 256];
    if (res) { v0 += res[base + tid]; v1 += res[base + tid + 256]; }

    float sum = v0 + v1;
    float sq  = v0 * v0 + v1 * v1;
#pragma unroll
    for (int off = 16; off > 0; off >>= 1) {
        sum += __shfl_xor_sync(0xffffffffu, sum, off);
        sq  += __shfl_xor_sync(0xffffffffu, sq,  off);
    }
    if (lane == 0) { rs[wid] = sum; rq[wid] = sq; }
    __syncthreads();
    if (tid == 0) {
        float S = 0.f, Q = 0.f;
#pragma unroll
        for (int i = 0; i < 8; i++) { S += rs[i]; Q += rq[i]; }
        float mean = S * (1.0f / HDIM);
        float var  = Q * (1.0f / HDIM) - mean * mean;
        stats[0] = mean;
        stats[1] = rsqrtf(var + 1e-5f);
    }
    __syncthreads();
    float mean = stats[0], inv = stats[1];
    out[base + tid]       = (v0 - mean) * inv * g[tid]       + bta[tid];
    out[base + tid + 256] = (v1 - mean) * inv * g[tid + 256] + bta[tid + 256];
}

// ---------------- tf32 mma flash attention ----------------------------------
// CTA: 64 q-rows, k-tiles of 128. 256 threads = 8 warps (4m x 2n).
// smem floats: Qs[64][68], KVs[128][72] (K at stride 68, V at stride 72),
//              Ms[64][132] (mask bias, then P), red/stat arrays.
__global__ __launch_bounds__(256,2) void attn_tf32(
    const float* __restrict__ qkv, const int* __restrict__ dist,
    float* __restrict__ out)
{
    extern __shared__ float sm[];
    float* Qs   = sm;               // 4352
    float* KVs  = Qs + 64*68;       // 9216
    float* Ms   = KVs + 128*72;     // 8448
    float* redm = Ms + 64*132;      // 128
    float* reds = redm + 128;       // 128
    float* rowM = reds + 128;       // 64
    float* rowL = rowM + 64;        // 64
    float* rowC = rowL + 64;        // 64
    uint32_t* Qsu = (uint32_t*)Qs;
    uint32_t* KVu = (uint32_t*)KVs;
    uint32_t* Msu = (uint32_t*)Ms;

    const int tid  = threadIdx.x;
    const int lane = tid & 31, wid = tid >> 5;
    const int g = lane >> 2, r = lane & 3;
    const int wm = wid & 3, wn = wid >> 2;
    const int q0 = blockIdx.x * 64, h = blockIdx.y, b = blockIdx.z;
    const size_t tokbase = (size_t)b * SLEN;
    const int qlo = wm*16 + g, qhi = qlo + 8;

    // load Q (pre-scaled by 1/sqrt(64), tf32-rounded)
    for (int i = tid; i < 64*16; i += 256){
        int row = i >> 4, c4 = (i & 15) << 2;
        float4 v = *(const float4*)(qkv + (tokbase + q0 + row)*1536 + h*64 + c4);
        uint32_t* d = Qsu + row*68 + c4;
        d[0]=f2tf(v.x*0.125f); d[1]=f2tf(v.y*0.125f);
        d[2]=f2tf(v.z*0.125f); d[3]=f2tf(v.w*0.125f);
    }
    if (tid < 64){ rowM[tid] = -1e30f; rowL[tid] = 0.f; }
    __syncthreads();

    // Q fragments live in registers across all k-tiles
    uint32_t qa[8][4];
#pragma unroll
    for (int kc=0; kc<8; kc++){
        qa[kc][0] = Qsu[qlo*68 + kc*8 + r  ];
        qa[kc][1] = Qsu[qhi*68 + kc*8 + r  ];
        qa[kc][2] = Qsu[qlo*68 + kc*8 + r+4];
        qa[kc][3] = Qsu[qhi*68 + kc*8 + r+4];
    }

    float o[4][4];
#pragma unroll
    for (int i=0;i<4;i++)
#pragma unroll
        for (int j=0;j<4;j++) o[i][j] = 0.f;

    for (int t = 0; t < 8; t++){
        const int k0 = t * 128;
        __syncthreads();   // prior tile's PV reads of KVs/Ms complete

        // K tile -> KVs (stride 68)
        for (int i = tid; i < 128*16; i += 256){
            int row = i >> 4, c4 = (i & 15) << 2;
            float4 v = *(const float4*)(qkv + (tokbase + k0 + row)*1536 + HDIM + h*64 + c4);
            uint32_t* d = KVu + row*68 + c4;
            d[0]=f2tf(v.x); d[1]=f2tf(v.y); d[2]=f2tf(v.z); d[3]=f2tf(v.w);
        }
        // mask bias -> Ms
        for (int i = tid; i < 64*32; i += 256){
            int q = i >> 5, c4 = (i & 31) << 2;
            const int* dr = dist + (size_t)b*SLEN*SLEN
                          + (h < 6 ? (size_t)(q0+q)*SLEN : 0) + k0 + c4;
            int4 dv = *(const int4*)dr;
            int qg = q0 + q;
            float* m = Ms + q*132 + c4;
            bool a0 = (h<4) ? (dv.x==1) : (dv.x>=1);
            bool a1 = (h<4) ? (dv.y==1) : (dv.y>=1);
            bool a2 = (h<4) ? (dv.z==1) : (dv.z>=1);
            bool a3 = (h<4) ? (dv.w==1) : (dv.w>=1);
            m[0] = (a0 || (k0+c4+0)==qg) ? 0.f : -1e9f;
            m[1] = (a1 || (k0+c4+1)==qg) ? 0.f : -1e9f;
            m[2] = (a2 || (k0+c4+2)==qg) ? 0.f : -1e9f;
            m[3] = (a3 || (k0+c4+3)==qg) ? 0.f : -1e9f;
        }
        __syncthreads();

        // scores S[64x128] via mma
        float s[8][4];
#pragma unroll
        for (int i=0;i<8;i++)
#pragma unroll
            for (int j=0;j<4;j++) s[i][j] = 0.f;
#pragma unroll
        for (int kc=0; kc<8; kc++){
#pragma unroll
            for (int nt=0; nt<8; nt++){
                int nb = wn*64 + nt*8;
                uint32_t b0 = KVu[(nb+g)*68 + kc*8 + r  ];
                uint32_t b1 = KVu[(nb+g)*68 + kc*8 + r+4];
                mma8(s[nt], qa[kc], b0, b1);
            }
        }

        // add mask, per-row tile max
        float mx0 = -1e30f, mx1 = -1e30f;
#pragma unroll
        for (int nt=0; nt<8; nt++){
            int cc = wn*64 + nt*8 + 2*r;
            s[nt][0] += Ms[qlo*132 + cc];   s[nt][1] += Ms[qlo*132 + cc+1];
            s[nt][2] += Ms[qhi*132 + cc];   s[nt][3] += Ms[qhi*132 + cc+1];
            mx0 = fmaxf(mx0, fmaxf(s[nt][0], s[nt][1]));
            mx1 = fmaxf(mx1, fmaxf(s[nt][2], s[nt][3]));
        }
        mx0 = fmaxf(mx0, __shfl_xor_sync(0xffffffffu, mx0, 1));
        mx0 = fmaxf(mx0, __shfl_xor_sync(0xffffffffu, mx0, 2));
        mx1 = fmaxf(mx1, __shfl_xor_sync(0xffffffffu, mx1, 1));
        mx1 = fmaxf(mx1, __shfl_xor_sync(0xffffffffu, mx1, 2));
        if (r == 0){ redm[qlo*2 + wn] = mx0; redm[qhi*2 + wn] = mx1; }
        __syncthreads();
        if (tid < 64){
            float mo = rowM[tid];
            float mn = fmaxf(mo, fmaxf(redm[tid*2], redm[tid*2+1]));
            rowC[tid] = __expf(mo - mn);
            rowM[tid] = mn;
        }
        __syncthreads();

        // exp, write P in place of mask, partial sums
        float mlo = rowM[qlo], mhi = rowM[qhi];
        float ps0 = 0.f, ps1 = 0.f;
#pragma unroll
        for (int nt=0; nt<8; nt++){
            int cc = wn*64 + nt*8 + 2*r;
            float p0 = __expf(s[nt][0]-mlo), p1 = __expf(s[nt][1]-mlo);
            float p2 = __expf(s[nt][2]-mhi), p3 = __expf(s[nt][3]-mhi);
            ps0 += p0 + p1;  ps1 += p2 + p3;
            Msu[qlo*132 + cc] = f2tf(p0);  Msu[qlo*132 + cc+1] = f2tf(p1);
            Msu[qhi*132 + cc] = f2tf(p2);  Msu[qhi*132 + cc+1] = f2tf(p3);
        }
        ps0 += __shfl_xor_sync(0xffffffffu, ps0, 1);
        ps0 += __shfl_xor_sync(0xffffffffu, ps0, 2);
        ps1 += __shfl_xor_sync(0xffffffffu, ps1, 1);
        ps1 += __shfl_xor_sync(0xffffffffu, ps1, 2);
        if (r == 0){ reds[qlo*2 + wn] = ps0; reds[qhi*2 + wn] = ps1; }

        // rescale O accumulators
        float clo = rowC[qlo], chi = rowC[qhi];
#pragma unroll
        for (int nt=0; nt<4; nt++){
            o[nt][0] *= clo; o[nt][1] *= clo;
            o[nt][2] *= chi; o[nt][3] *= chi;
        }
        __syncthreads();
        if (tid < 64) rowL[tid] = rowL[tid]*rowC[tid] + reds[tid*2] + reds[tid*2+1];

        // V tile -> KVs (stride 72; conflict-free B-frag reads)
        for (int i = tid; i < 128*16; i += 256){
            int row = i >> 4, c4 = (i & 15) << 2;
            float4 v = *(const float4*)(qkv + (tokbase + k0 + row)*1536 + 2*HDIM + h*64 + c4);
            uint32_t* d = KVu + row*72 + c4;
            d[0]=f2tf(v.x); d[1]=f2tf(v.y); d[2]=f2tf(v.z); d[3]=f2tf(v.w);
        }
        __syncthreads();

        // O += P @ V
#pragma unroll
        for (int kc=0; kc<16; kc++){
            uint32_t pa[4];
            pa[0] = Msu[qlo*132 + kc*8 + r  ];
            pa[1] = Msu[qhi*132 + kc*8 + r  ];
            pa[2] = Msu[qlo*132 + kc*8 + r+4];
            pa[3] = Msu[qhi*132 + kc*8 + r+4];
#pragma unroll
            for (int nt=0; nt<4; nt++){
                int db = wn*32 + nt*8;
                uint32_t b0 = KVu[(kc*8+r  )*72 + db + g];
                uint32_t b1 = KVu[(kc*8+r+4)*72 + db + g];
                mma8(o[nt], pa, b0, b1);
            }
        }
    }
    __syncthreads();

    float llo = 1.f / rowL[qlo];
    float lhi = 1.f / rowL[qhi];
    size_t rlo = (tokbase + q0 + qlo) * HDIM;
    size_t rhi = (tokbase + q0 + qhi) * HDIM;
#pragma unroll
    for (int nt=0; nt<4; nt++){
        int cc = h*64 + wn*32 + nt*8 + 2*r;
        *(float2*)(out + rlo + cc) = make_float2(o[nt][0]*llo, o[nt][1]*llo);
        *(float2*)(out + rhi + cc) = make_float2(o[nt][2]*lhi, o[nt][3]*lhi);
    }
}

// ---------------- final batchnorm over batch of 8 at s=0 --------------------
__global__ void bn_kernel(const float* __restrict__ x, const float* __restrict__ g,
                          const float* __restrict__ bta, float* __restrict__ out)
{
    int c = threadIdx.x;
    float v[BSZ];
    float s = 0.f;
#pragma unroll
    for (int b = 0; b < BSZ; b++) {
        v[b] = x[((size_t)b * SLEN) * HDIM + c];
        s += v[b];
    }
    float mean = s * (1.0f / BSZ);
    float q = 0.f;
#pragma unroll
    for (int b = 0; b < BSZ; b++) { float d = v[b] - mean; q += d * d; }
    float inv = rsqrtf(q * (1.0f / BSZ) + 1e-5f);
#pragma unroll
    for (int b = 0; b < BSZ; b++)
        out[b * HDIM + c] = (v[b] - mean) * inv * g[c] + bta[c];
}

// ---------------- launcher --------------------------------------------------
#define GEMM_SMEM 55296
#define ATTN_SMEM 89856

extern "C" void kernel_launch(void* const* d_in, const int* in_sizes, int n_in,
                              void* d_out, int out_size)
{
    const float* nodes   = (const float*)d_in[0];
    const int*   dist    = (const int*)  d_in[1];
    const float* dense_w = (const float*)d_in[2];
    const float* dense_b = (const float*)d_in[3];
    const float* dln_g   = (const float*)d_in[4];
    const float* dln_b   = (const float*)d_in[5];
    const float* qkv_w   = (const float*)d_in[6];
    const float* qkv_b   = (const float*)d_in[7];
    const float* out_w   = (const float*)d_in[8];
    const float* out_b   = (const float*)d_in[9];
    const float* ln1_g   = (const float*)d_in[10];
    const float* ln1_b   = (const float*)d_in[11];
    const float* w1      = (const float*)d_in[12];
    const float* b1      = (const float*)d_in[13];
    const float* w2      = (const float*)d_in[14];
    const float* b2      = (const float*)d_in[15];
    const float* ln2_g   = (const float*)d_in[16];
    const float* ln2_b   = (const float*)d_in[17];
    const float* bn_g    = (const float*)d_in[18];
    const float* bn_b    = (const float*)d_in[19];
    float* out = (float*)d_out;

    float *xin, *x, *tmp, *qkv, *attn, *ff;
    cudaGetSymbolAddress((void**)&xin,  g_xin);
    cudaGetSymbolAddress((void**)&x,    g_x);
    cudaGetSymbolAddress((void**)&tmp,  g_tmp);
    cudaGetSymbolAddress((void**)&qkv,  g_qkv);
    cudaGetSymbolAddress((void**)&attn, g_attn);
    cudaGetSymbolAddress((void**)&ff,   g_ff);

    cudaFuncSetAttribute(gemm_tf32, cudaFuncAttributeMaxDynamicSharedMemorySize, GEMM_SMEM);
    cudaFuncSetAttribute(attn_tf32, cudaFuncAttributeMaxDynamicSharedMemorySize, ATTN_SMEM);

    // dense + LN
    transpose_kernel<<<NTOK, IDIM>>>(nodes, xin);
    gemm_tf32<<<dim3(HDIM/64, NTOK/128), 256, GEMM_SMEM>>>(
        xin, dense_w, dense_b, tmp, NTOK, HDIM, IDIM, 0);
    ln_kernel<<<NTOK, 256>>>(tmp, nullptr, dln_g, dln_b, x);

    for (int l = 0; l < NLAYER; l++) {
        gemm_tf32<<<dim3(3*HDIM/64, NTOK/128), 256, GEMM_SMEM>>>(
            x, qkv_w + (size_t)l*3*HDIM*HDIM, qkv_b + (size_t)l*3*HDIM,
            qkv, NTOK, 3*HDIM, HDIM, 0);
        attn_tf32<<<dim3(SLEN/64, NHEAD, BSZ), 256, ATTN_SMEM>>>(qkv, dist, attn);
        gemm_tf32<<<dim3(HDIM/64, NTOK/128), 256, GEMM_SMEM>>>(
            attn, out_w + (size_t)l*HDIM*HDIM, out_b + (size_t)l*HDIM,
            tmp, NTOK, HDIM, HDIM, 0);
        ln_kernel<<<NTOK, 256>>>(tmp, x, ln1_g + (size_t)l*HDIM,
                                 ln1_b + (size_t)l*HDIM, x);
        gemm_tf32<<<dim3(FFDIM/64, NTOK/128), 256, GEMM_SMEM>>>(
            x, w1 + (size_t)l*FFDIM*HDIM, b1 + (size_t)l*FFDIM,
            ff, NTOK, FFDIM, HDIM, 1);
        gemm_tf32<<<dim3(HDIM/64, NTOK/128), 256, GEMM_SMEM>>>(
            ff, w2 + (size_t)l*HDIM*FFDIM, b2 + (size_t)l*HDIM,
            tmp, NTOK, HDIM, FFDIM, 0);
        ln_kernel<<<NTOK, 256>>>(tmp, x, ln2_g + (size_t)l*HDIM,
                                 ln2_b + (size_t)l*HDIM, x);
    }

    bn_kernel<<<1, HDIM>>>(x, bn_g, bn_b, out);
}

// round 3
// speedup vs baseline: 6.4483x; 1.2637x over previous
#include <cuda_runtime.h>
#include <math.h>
#include <stdint.h>

// Problem constants
#define SLEN 1024
#define BSZ  8
#define IDIM 256
#define HDIM 512
#define NHEAD 8
#define HD 64
#define FFDIM 1024
#define NLAYER 4
#define NTOK (SLEN*BSZ)   // 8192

// ---------------- scratch (device globals; no allocation allowed) -----------
__device__ float g_xin [NTOK * IDIM];     // tf32 bits
__device__ float g_x   [NTOK * HDIM];     // fp32 (residual stream)
__device__ float g_xc  [NTOK * HDIM];     // tf32 bits copy of x
__device__ float g_tmp [NTOK * HDIM];     // fp32
__device__ float g_qkv [NTOK * 3*HDIM];   // tf32 bits
__device__ float g_attn[NTOK * HDIM];     // tf32 bits
__device__ float g_ff  [NTOK * FFDIM];    // tf32 bits
__device__ float g_w   [8519680];         // all weights, tf32 bits
__device__ uint32_t g_mask[3 * BSZ * SLEN * 32];  // packed allow-bits per class

// weight offsets in g_w
#define OFF_DENSE 0
#define OFF_QKV   131072
#define OFF_OUT   3276800
#define OFF_FF1   4325376
#define OFF_FF2   6422528

// ---------------- helpers ---------------------------------------------------
__device__ __forceinline__ uint32_t f2tf(float x){
    uint32_t r; asm("cvt.rna.tf32.f32 %0, %1;" : "=r"(r) : "f"(x)); return r;
}
__device__ __forceinline__ void mma8(float* c, const uint32_t* a, uint32_t b0, uint32_t b1){
    asm volatile(
        "mma.sync.aligned.m16n8k8.row.col.f32.tf32.tf32.f32 "
        "{%0,%1,%2,%3},{%4,%5,%6,%7},{%8,%9},{%0,%1,%2,%3};"
        : "+f"(c[0]),"+f"(c[1]),"+f"(c[2]),"+f"(c[3])
        : "r"(a[0]),"r"(a[1]),"r"(a[2]),"r"(a[3]),"r"(b0),"r"(b1));
}
__device__ __forceinline__ void cpa16(uint32_t s, const void* g){
    asm volatile("cp.async.cg.shared.global [%0], [%1], 16;" :: "r"(s),"l"(g));
}
__device__ __forceinline__ void cpacommit(){ asm volatile("cp.async.commit_group;"); }
__device__ __forceinline__ void cpawait1(){ asm volatile("cp.async.wait_group 1;"); }
__device__ __forceinline__ void cpawait0(){ asm volatile("cp.async.wait_group 0;"); }

// ---------------- elementwise tf32 conversion (weights) ---------------------
__global__ void cvt4_kernel(const float4* __restrict__ src, float4* __restrict__ dst, int n4)
{
    int i = blockIdx.x * 256 + threadIdx.x;
    if (i >= n4) return;
    float4 v = src[i];
    float4 o;
    o.x = __uint_as_float(f2tf(v.x));
    o.y = __uint_as_float(f2tf(v.y));
    o.z = __uint_as_float(f2tf(v.z));
    o.w = __uint_as_float(f2tf(v.w));
    dst[i] = o;
}

// ---------------- mask bit precompute ---------------------------------------
// For each (b,q,32-key word): short: d==1, long: d>=1, glob: d[b,0,k]>=1; all OR diag.
__global__ void mask_kernel(const int* __restrict__ dist, uint32_t* __restrict__ mask)
{
    int b = blockIdx.y;
    int q = blockIdx.x * 8 + (threadIdx.x >> 5);
    int w = threadIdx.x & 31;
    const int4* dr = (const int4*)(dist + ((size_t)b*SLEN + q)*SLEN + w*32);
    const int4* d0 = (const int4*)(dist + (size_t)b*SLEN*SLEN + w*32);
    uint32_t sb = 0, lb = 0, gb = 0;
#pragma unroll
    for (int p = 0; p < 8; p++){
        int4 d = dr[p], dg = d0[p];
        int j = p*4;
        sb |= (uint32_t)(d.x==1)<<j | (uint32_t)(d.y==1)<<(j+1)
            | (uint32_t)(d.z==1)<<(j+2) | (uint32_t)(d.w==1)<<(j+3);
        lb |= (uint32_t)(d.x>=1)<<j | (uint32_t)(d.y>=1)<<(j+1)
            | (uint32_t)(d.z>=1)<<(j+2) | (uint32_t)(d.w>=1)<<(j+3);
        gb |= (uint32_t)(dg.x>=1)<<j | (uint32_t)(dg.y>=1)<<(j+1)
            | (uint32_t)(dg.z>=1)<<(j+2) | (uint32_t)(dg.w>=1)<<(j+3);
    }
    if ((q >> 5) == w){ uint32_t e = 1u << (q & 31); sb |= e; lb |= e; gb |= e; }
    size_t o = ((size_t)b*SLEN + q)*32 + w;
    mask[o] = sb;
    mask[(size_t)BSZ*SLEN*32 + o] = lb;
    mask[(size_t)2*BSZ*SLEN*32 + o] = gb;
}

// ---------------- transpose nodes (S,B,I) -> x_in (B*S, I), tf32 ------------
__global__ void transpose_kernel(const float* __restrict__ nodes, float* __restrict__ xin)
{
    int token = blockIdx.x;
    int b = token >> 10;
    int s = token & 1023;
    float v = nodes[((size_t)s * BSZ + b) * IDIM + threadIdx.x];
    xin[(size_t)token * IDIM + threadIdx.x] = __uint_as_float(f2tf(v));
}

// ---------------- tf32 tensor-core GEMM: C[M,N] = A[M,K] @ W[N,K]^T + bias --
// CTA 128x128, BK=32, 256 threads = 8 warps (2m x 4n), warp tile 64x32.
// A, W already hold tf32 bits. flags: bit0 = relu, bit1 = store tf32 bits.
__global__ __launch_bounds__(256,2) void gemm_tf32(
    const float* __restrict__ A, const float* __restrict__ W,
    const float* __restrict__ bias, float* __restrict__ C,
    int M, int N, int K, int flags)
{
    extern __shared__ uint32_t smu[];
    uint32_t* sA = smu;             // 2 stages * 4608
    uint32_t* sB = smu + 9216;      // 2 stages * 4608

    const int tid  = threadIdx.x;
    const int lane = tid & 31, wid = tid >> 5;
    const int g = lane >> 2, r = lane & 3;
    const int wm = wid & 1, wn = wid >> 1;
    const int row0 = blockIdx.y * 128, col0 = blockIdx.x * 128;

    const uint32_t sAb = (uint32_t)__cvta_generic_to_shared(sA);
    const uint32_t sBb = (uint32_t)__cvta_generic_to_shared(sB);

    float c[4][4][4];
#pragma unroll
    for (int i=0;i<4;i++)
#pragma unroll
        for (int j=0;j<4;j++)
#pragma unroll
            for (int k=0;k<4;k++) c[i][j][k] = 0.f;

    const int nbk = K >> 5;

    auto issue = [&](int bk, int st){
#pragma unroll
        for (int p=0;p<4;p++){
            int idx = tid + p*256;
            int row = idx >> 3, c4 = (idx & 7) << 2;
            cpa16(sAb + (uint32_t)(st*4608 + row*36 + c4)*4,
                  A + (size_t)(row0 + row)*K + bk*32 + c4);
            cpa16(sBb + (uint32_t)(st*4608 + row*36 + c4)*4,
                  W + (size_t)(col0 + row)*K + bk*32 + c4);
        }
        cpacommit();
    };

    issue(0, 0);
    for (int bk = 0; bk < nbk; bk++){
        int st = bk & 1;
        if (bk+1 < nbk){ issue(bk+1, st^1); cpawait1(); }
        else           { cpawait0(); }
        __syncthreads();
        const uint32_t* a_s = sA + st*4608;
        const uint32_t* b_s = sB + st*4608;
#pragma unroll
        for (int kc=0; kc<4; kc++){
            uint32_t a[4][4];
#pragma unroll
            for (int mt=0; mt<4; mt++){
                int mb = wm*64 + mt*16;
                a[mt][0] = a_s[(mb+g  )*36 + kc*8 + r  ];
                a[mt][1] = a_s[(mb+g+8)*36 + kc*8 + r  ];
                a[mt][2] = a_s[(mb+g  )*36 + kc*8 + r+4];
                a[mt][3] = a_s[(mb+g+8)*36 + kc*8 + r+4];
            }
#pragma unroll
            for (int nt=0; nt<4; nt++){
                int nb = wn*32 + nt*8;
                uint32_t b0 = b_s[(nb+g)*36 + kc*8 + r  ];
                uint32_t b1 = b_s[(nb+g)*36 + kc*8 + r+4];
#pragma unroll
                for (int mt=0; mt<4; mt++) mma8(c[mt][nt], a[mt], b0, b1);
            }
        }
        __syncthreads();
    }

    const int relu = flags & 1, cvt = flags & 2;
#pragma unroll
    for (int mt=0; mt<4; mt++){
#pragma unroll
        for (int nt=0; nt<4; nt++){
            int rr = row0 + wm*64 + mt*16 + g;
            int cc = col0 + wn*32 + nt*8 + 2*r;
            float b0 = bias[cc], b1 = bias[cc+1];
            float v0 = c[mt][nt][0] + b0, v1 = c[mt][nt][1] + b1;
            float v2 = c[mt][nt][2] + b0, v3 = c[mt][nt][3] + b1;
            if (relu){ v0=fmaxf(v0,0.f); v1=fmaxf(v1,0.f); v2=fmaxf(v2,0.f); v3=fmaxf(v3,0.f); }
            if (cvt){
                v0 = __uint_as_float(f2tf(v0)); v1 = __uint_as_float(f2tf(v1));
                v2 = __uint_as_float(f2tf(v2)); v3 = __uint_as_float(f2tf(v3));
            }
            *(float2*)(C + (size_t)rr*N + cc)     = make_float2(v0, v1);
            *(float2*)(C + (size_t)(rr+8)*N + cc) = make_float2(v2, v3);
        }
    }
}

// ---------------- LayerNorm row kernel (H=512), optional residual -----------
// Writes fp32 result to out and tf32 bits to outc.
__global__ __launch_bounds__(256) void ln_kernel(
    const float* __restrict__ y, const float* __restrict__ res,
    const float* __restrict__ g, const float* __restrict__ bta,
    float* __restrict__ out, float* __restrict__ outc)
{
    __shared__ float rs[8], rq[8], stats[2];
    int tid = threadIdx.x;
    int lane = tid & 31, wid = tid >> 5;
    size_t base = (size_t)blockIdx.x * HDIM;

    float v0 = y[base + tid];
    float v1 = y[base + tid + 256];
    if (res) { v0 += res[base + tid]; v1 += res[base + tid + 256]; }

    float sum = v0 + v1;
    float sq  = v0 * v0 + v1 * v1;
#pragma unroll
    for (int off = 16; off > 0; off >>= 1) {
        sum += __shfl_xor_sync(0xffffffffu, sum, off);
        sq  += __shfl_xor_sync(0xffffffffu, sq,  off);
    }
    if (lane == 0) { rs[wid] = sum; rq[wid] = sq; }
    __syncthreads();
    if (tid == 0) {
        float S = 0.f, Q = 0.f;
#pragma unroll
        for (int i = 0; i < 8; i++) { S += rs[i]; Q += rq[i]; }
        float mean = S * (1.0f / HDIM);
        float var  = Q * (1.0f / HDIM) - mean * mean;
        stats[0] = mean;
        stats[1] = rsqrtf(var + 1e-5f);
    }
    __syncthreads();
    float mean = stats[0], inv = stats[1];
    float o0 = (v0 - mean) * inv * g[tid]       + bta[tid];
    float o1 = (v1 - mean) * inv * g[tid + 256] + bta[tid + 256];
    out[base + tid]        = o0;
    out[base + tid + 256]  = o1;
    outc[base + tid]       = __uint_as_float(f2tf(o0));
    outc[base + tid + 256] = __uint_as_float(f2tf(o1));
}

// ---------------- tf32 mma flash attention ----------------------------------
// CTA: 64 q-rows, k-tiles of 128. 256 threads = 8 warps (4m x 2n).
// qkv holds tf32 bits. Masks come from packed bit arrays.
__global__ __launch_bounds__(256,2) void attn_tf32(
    const float* __restrict__ qkv, const uint32_t* __restrict__ maskall,
    float* __restrict__ out)
{
    extern __shared__ float sm[];
    float* Qs   = sm;                 // 64*68   = 4352
    float* KVs  = Qs + 64*68;         // 128*72  = 9216
    float* Ms   = KVs + 128*72;       // 64*132  = 8448
    uint32_t* msku = (uint32_t*)(Ms + 64*132);  // 256
    float* redm = Ms + 64*132 + 256;  // 128
    float* reds = redm + 128;         // 128
    float* rowM = reds + 128;         // 64
    float* rowL = rowM + 64;          // 64
    float* rowC = rowL + 64;          // 64
    uint32_t* KVu = (uint32_t*)KVs;
    uint32_t* Msu = (uint32_t*)Ms;

    const int tid  = threadIdx.x;
    const int lane = tid & 31, wid = tid >> 5;
    const int g = lane >> 2, r = lane & 3;
    const int wm = wid & 3, wn = wid >> 2;
    const int q0 = blockIdx.x * 64, h = blockIdx.y, b = blockIdx.z;
    const size_t tokbase = (size_t)b * SLEN;
    const int qlo = wm*16 + g, qhi = qlo + 8;

    const int cls = (h < 4) ? 0 : (h < 6) ? 1 : 2;
    const uint32_t* mbase = maskall + (size_t)cls*BSZ*SLEN*32 + (size_t)b*SLEN*32;

    const uint32_t Qb  = (uint32_t)__cvta_generic_to_shared(Qs);
    const uint32_t KVb = (uint32_t)__cvta_generic_to_shared(KVs);

    // Q tile via cp.async (tf32 bits already)
#pragma unroll
    for (int p=0;p<4;p++){
        int i = tid + p*256;
        int row = i >> 4, c4 = (i & 15) << 2;
        cpa16(Qb + (uint32_t)(row*68 + c4)*4,
              qkv + (tokbase + q0 + row)*1536 + h*64 + c4);
    }
    cpacommit();
    if (tid < 64){ rowM[tid] = -1e30f; rowL[tid] = 0.f; }
    cpawait0();
    __syncthreads();

    // Q fragments (scaled by 1/sqrt(64); exact exponent shift keeps tf32 form)
    uint32_t qa[8][4];
#pragma unroll
    for (int kc=0; kc<8; kc++){
        qa[kc][0] = __float_as_uint(Qs[qlo*68 + kc*8 + r  ] * 0.125f);
        qa[kc][1] = __float_as_uint(Qs[qhi*68 + kc*8 + r  ] * 0.125f);
        qa[kc][2] = __float_as_uint(Qs[qlo*68 + kc*8 + r+4] * 0.125f);
        qa[kc][3] = __float_as_uint(Qs[qhi*68 + kc*8 + r+4] * 0.125f);
    }

    float o[4][4];
#pragma unroll
    for (int i=0;i<4;i++)
#pragma unroll
        for (int j=0;j<4;j++) o[i][j] = 0.f;

    for (int t = 0; t < 8; t++){
        const int k0 = t * 128;
        __syncthreads();   // prior tile's PV reads of KVs/Ms complete

        // K tile -> KVs (stride 68) via cp.async
#pragma unroll
        for (int p=0;p<8;p++){
            int i = tid + p*256;
            int row = i >> 4, c4 = (i & 15) << 2;
            cpa16(KVb + (uint32_t)(row*68 + c4)*4,
                  qkv + (tokbase + k0 + row)*1536 + HDIM + h*64 + c4);
        }
        cpacommit();
        // mask words for this tile: 64 rows x 4 words
        {
            int row = tid >> 2, w = tid & 3;
            msku[tid] = mbase[(size_t)(q0 + row)*32 + t*4 + w];
        }
        cpawait0();
        __syncthreads();

        // scores S[64x128] via mma
        float s[8][4];
#pragma unroll
        for (int i=0;i<8;i++)
#pragma unroll
            for (int j=0;j<4;j++) s[i][j] = 0.f;
#pragma unroll
        for (int kc=0; kc<8; kc++){
#pragma unroll
            for (int nt=0; nt<8; nt++){
                int nb = wn*64 + nt*8;
                uint32_t b0 = KVu[(nb+g)*68 + kc*8 + r  ];
                uint32_t b1 = KVu[(nb+g)*68 + kc*8 + r+4];
                mma8(s[nt], qa[kc], b0, b1);
            }
        }
        __syncthreads();   // K reads done

        // V tile -> KVs (stride 72) via cp.async; overlaps with softmax below
#pragma unroll
        for (int p=0;p<8;p++){
            int i = tid + p*256;
            int row = i >> 4, c4 = (i & 15) << 2;
            cpa16(KVb + (uint32_t)(row*72 + c4)*4,
                  qkv + (tokbase + k0 + row)*1536 + 2*HDIM + h*64 + c4);
        }
        cpacommit();

        // mask apply (bit test) + per-row tile max
        uint32_t wl0 = msku[qlo*4 + wn*2], wl1 = msku[qlo*4 + wn*2 + 1];
        uint32_t wh0 = msku[qhi*4 + wn*2], wh1 = msku[qhi*4 + wn*2 + 1];
        float mx0 = -1e30f, mx1 = -1e30f;
#pragma unroll
        for (int nt=0; nt<8; nt++){
            uint32_t wlo = (nt < 4) ? wl0 : wl1;
            uint32_t whi = (nt < 4) ? wh0 : wh1;
            int sh = (nt & 3)*8 + 2*r;
            s[nt][0] = ((wlo >> sh)     & 1) ? s[nt][0] : -1e9f;
            s[nt][1] = ((wlo >> (sh+1)) & 1) ? s[nt][1] : -1e9f;
            s[nt][2] = ((whi >> sh)     & 1) ? s[nt][2] : -1e9f;
            s[nt][3] = ((whi >> (sh+1)) & 1) ? s[nt][3] : -1e9f;
            mx0 = fmaxf(mx0, fmaxf(s[nt][0], s[nt][1]));
            mx1 = fmaxf(mx1, fmaxf(s[nt][2], s[nt][3]));
        }
        mx0 = fmaxf(mx0, __shfl_xor_sync(0xffffffffu, mx0, 1));
        mx0 = fmaxf(mx0, __shfl_xor_sync(0xffffffffu, mx0, 2));
        mx1 = fmaxf(mx1, __shfl_xor_sync(0xffffffffu, mx1, 1));
        mx1 = fmaxf(mx1, __shfl_xor_sync(0xffffffffu, mx1, 2));
        if (r == 0){ redm[qlo*2 + wn] = mx0; redm[qhi*2 + wn] = mx1; }
        __syncthreads();
        if (tid < 64){
            float mo = rowM[tid];
            float mn = fmaxf(mo, fmaxf(redm[tid*2], redm[tid*2+1]));
            rowC[tid] = __expf(mo - mn);
            rowM[tid] = mn;
        }
        __syncthreads();

        // exp, write P (tf32) to Ms, partial sums
        float mlo = rowM[qlo], mhi = rowM[qhi];
        float ps0 = 0.f, ps1 = 0.f;
#pragma unroll
        for (int nt=0; nt<8; nt++){
            int cc = wn*64 + nt*8 + 2*r;
            float p0 = __expf(s[nt][0]-mlo), p1 = __expf(s[nt][1]-mlo);
            float p2 = __expf(s[nt][2]-mhi), p3 = __expf(s[nt][3]-mhi);
            ps0 += p0 + p1;  ps1 += p2 + p3;
            Msu[qlo*132 + cc] = f2tf(p0);  Msu[qlo*132 + cc+1] = f2tf(p1);
            Msu[qhi*132 + cc] = f2tf(p2);  Msu[qhi*132 + cc+1] = f2tf(p3);
        }
        ps0 += __shfl_xor_sync(0xffffffffu, ps0, 1);
        ps0 += __shfl_xor_sync(0xffffffffu, ps0, 2);
        ps1 += __shfl_xor_sync(0xffffffffu, ps1, 1);
        ps1 += __shfl_xor_sync(0xffffffffu, ps1, 2);
        if (r == 0){ reds[qlo*2 + wn] = ps0; reds[qhi*2 + wn] = ps1; }

        // rescale O accumulators
        float clo = rowC[qlo], chi = rowC[qhi];
#pragma unroll
        for (int nt=0; nt<4; nt++){
            o[nt][0] *= clo; o[nt][1] *= clo;
            o[nt][2] *= chi; o[nt][3] *= chi;
        }
        cpawait0();        // V in smem
        __syncthreads();   // V + P + reds visible
        if (tid < 64) rowL[tid] = rowL[tid]*rowC[tid] + reds[tid*2] + reds[tid*2+1];

        // O += P @ V
#pragma unroll
        for (int kc=0; kc<16; kc++){
            uint32_t pa[4];
            pa[0] = Msu[qlo*132 + kc*8 + r  ];
            pa[1] = Msu[qhi*132 + kc*8 + r  ];
            pa[2] = Msu[qlo*132 + kc*8 + r+4];
            pa[3] = Msu[qhi*132 + kc*8 + r+4];
#pragma unroll
            for (int nt=0; nt<4; nt++){
                int db = wn*32 + nt*8;
                uint32_t b0 = KVu[(kc*8+r  )*72 + db + g];
                uint32_t b1 = KVu[(kc*8+r+4)*72 + db + g];
                mma8(o[nt], pa, b0, b1);
            }
        }
    }
    __syncthreads();

    float llo = 1.f / rowL[qlo];
    float lhi = 1.f / rowL[qhi];
    size_t rlo = (tokbase + q0 + qlo) * HDIM;
    size_t rhi = (tokbase + q0 + qhi) * HDIM;
#pragma unroll
    for (int nt=0; nt<4; nt++){
        int cc = h*64 + wn*32 + nt*8 + 2*r;
        float v0 = __uint_as_float(f2tf(o[nt][0]*llo));
        float v1 = __uint_as_float(f2tf(o[nt][1]*llo));
        float v2 = __uint_as_float(f2tf(o[nt][2]*lhi));
        float v3 = __uint_as_float(f2tf(o[nt][3]*lhi));
        *(float2*)(out + rlo + cc) = make_float2(v0, v1);
        *(float2*)(out + rhi + cc) = make_float2(v2, v3);
    }
}

// ---------------- final batchnorm over batch of 8 at s=0 --------------------
__global__ void bn_kernel(const float* __restrict__ x, const float* __restrict__ g,
                          const float* __restrict__ bta, float* __restrict__ out)
{
    int c = threadIdx.x;
    float v[BSZ];
    float s = 0.f;
#pragma unroll
    for (int b = 0; b < BSZ; b++) {
        v[b] = x[((size_t)b * SLEN) * HDIM + c];
        s += v[b];
    }
    float mean = s * (1.0f / BSZ);
    float q = 0.f;
#pragma unroll
    for (int b = 0; b < BSZ; b++) { float d = v[b] - mean; q += d * d; }
    float inv = rsqrtf(q * (1.0f / BSZ) + 1e-5f);
#pragma unroll
    for (int b = 0; b < BSZ; b++)
        out[b * HDIM + c] = (v[b] - mean) * inv * g[c] + bta[c];
}

// ---------------- launcher --------------------------------------------------
#define GEMM_SMEM 73728
#define ATTN_SMEM 90880

extern "C" void kernel_launch(void* const* d_in, const int* in_sizes, int n_in,
                              void* d_out, int out_size)
{
    const float* nodes   = (const float*)d_in[0];
    const int*   dist    = (const int*)  d_in[1];
    const float* dense_w = (const float*)d_in[2];
    const float* dense_b = (const float*)d_in[3];
    const float* dln_g   = (const float*)d_in[4];
    const float* dln_b   = (const float*)d_in[5];
    const float* qkv_w   = (const float*)d_in[6];
    const float* qkv_b   = (const float*)d_in[7];
    const float* out_w   = (const float*)d_in[8];
    const float* out_b   = (const float*)d_in[9];
    const float* ln1_g   = (const float*)d_in[10];
    const float* ln1_b   = (const float*)d_in[11];
    const float* w1      = (const float*)d_in[12];
    const float* b1      = (const float*)d_in[13];
    const float* w2      = (const float*)d_in[14];
    const float* b2      = (const float*)d_in[15];
    const float* ln2_g   = (const float*)d_in[16];
    const float* ln2_b   = (const float*)d_in[17];
    const float* bn_g    = (const float*)d_in[18];
    const float* bn_b    = (const float*)d_in[19];
    float* out = (float*)d_out;

    float *xin, *x, *xc, *tmp, *qkv, *attn, *ff, *wbuf;
    uint32_t* mask;
    cudaGetSymbolAddress((void**)&xin,  g_xin);
    cudaGetSymbolAddress((void**)&x,    g_x);
    cudaGetSymbolAddress((void**)&xc,   g_xc);
    cudaGetSymbolAddress((void**)&tmp,  g_tmp);
    cudaGetSymbolAddress((void**)&qkv,  g_qkv);
    cudaGetSymbolAddress((void**)&attn, g_attn);
    cudaGetSymbolAddress((void**)&ff,   g_ff);
    cudaGetSymbolAddress((void**)&wbuf, g_w);
    cudaGetSymbolAddress((void**)&mask, g_mask);

    cudaFuncSetAttribute(gemm_tf32, cudaFuncAttributeMaxDynamicSharedMemorySize, GEMM_SMEM);
    cudaFuncSetAttribute(attn_tf32, cudaFuncAttributeMaxDynamicSharedMemorySize, ATTN_SMEM);

    // one-time-per-launch preprocessing
    cvt4_kernel<<<128,  256>>>((const float4*)dense_w, (float4*)(wbuf + OFF_DENSE), 32768);
    cvt4_kernel<<<3072, 256>>>((const float4*)qkv_w,   (float4*)(wbuf + OFF_QKV),   786432);
    cvt4_kernel<<<1024, 256>>>((const float4*)out_w,   (float4*)(wbuf + OFF_OUT),   262144);
    cvt4_kernel<<<2048, 256>>>((const float4*)w1,      (float4*)(wbuf + OFF_FF1),   524288);
    cvt4_kernel<<<2048, 256>>>((const float4*)w2,      (float4*)(wbuf + OFF_FF2),   524288);
    mask_kernel<<<dim3(SLEN/8, BSZ), 256>>>(dist, mask);
    transpose_kernel<<<NTOK, IDIM>>>(nodes, xin);

    // dense + LN
    gemm_tf32<<<dim3(HDIM/128, NTOK/128), 256, GEMM_SMEM>>>(
        xin, wbuf + OFF_DENSE, dense_b, tmp, NTOK, HDIM, IDIM, 0);
    ln_kernel<<<NTOK, 256>>>(tmp, nullptr, dln_g, dln_b, x, xc);

    for (int l = 0; l < NLAYER; l++) {
        gemm_tf32<<<dim3(3*HDIM/128, NTOK/128), 256, GEMM_SMEM>>>(
            xc, wbuf + OFF_QKV + (size_t)l*3*HDIM*HDIM, qkv_b + (size_t)l*3*HDIM,
            qkv, NTOK, 3*HDIM, HDIM, 2);
        attn_tf32<<<dim3(SLEN/64, NHEAD, BSZ), 256, ATTN_SMEM>>>(qkv, mask, attn);
        gemm_tf32<<<dim3(HDIM/128, NTOK/128), 256, GEMM_SMEM>>>(
            attn, wbuf + OFF_OUT + (size_t)l*HDIM*HDIM, out_b + (size_t)l*HDIM,
            tmp, NTOK, HDIM, HDIM, 0);
        ln_kernel<<<NTOK, 256>>>(tmp, x, ln1_g + (size_t)l*HDIM,
                                 ln1_b + (size_t)l*HDIM, x, xc);
        gemm_tf32<<<dim3(FFDIM/128, NTOK/128), 256, GEMM_SMEM>>>(
            xc, wbuf + OFF_FF1 + (size_t)l*FFDIM*HDIM, b1 + (size_t)l*FFDIM,
            ff, NTOK, FFDIM, HDIM, 3);
        gemm_tf32<<<dim3(HDIM/128, NTOK/128), 256, GEMM_SMEM>>>(
            ff, wbuf + OFF_FF2 + (size_t)l*HDIM*FFDIM, b2 + (size_t)l*HDIM,
            tmp, NTOK, HDIM, FFDIM, 0);
        ln_kernel<<<NTOK, 256>>>(tmp, x, ln2_g + (size_t)l*HDIM,
                                 ln2_b + (size_t)l*HDIM, x, xc);
    }

    bn_kernel<<<1, HDIM>>>(x, bn_g, bn_b, out);
}